// round 1
// baseline (speedup 1.0000x reference)
#include <cuda_runtime.h>

// ModularTreeMLPPredictor: heap-indexed binary tree of per-level MLPs.
// out[b, g] for node g at level l (g = 2^l - 1 + i) is MLP_l applied to
// [features[b,g,:32], out[b,2g+1], out[b,2g+2], treatment[b]].
// Levels run bottom-up (l = 10 .. 0); leaf level uses zeros for children.
//
// Inputs (metadata order):
//   d_in[0] features  float32 [512, 2047, 32]
//   d_in[1] treatment float32 [512]
//   d_in[2] W1        float32 [11, 35, 64]
//   d_in[3] b1        float32 [11, 64]
//   d_in[4] W2        float32 [11, 64, 64]
//   d_in[5] b2        float32 [11, 64]
//   d_in[6] W3        float32 [11, 64, 1]
//   d_in[7] b3        float32 [11, 1]
// Output: float32 [512, 2047]

namespace {

constexpr int kD   = 11;
constexpr int kF   = 32;
constexpr int kH   = 64;
constexpr int kB   = 512;
constexpr int kN   = 2047;   // 2^11 - 1
constexpr int kFin = kF + 3; // 35

constexpr int kThreads = 128;
constexpr int kMaxGrid = 444; // 3 CTAs/SM * 148 SMs

__global__ __launch_bounds__(kThreads, 3)
void tree_level_kernel(const float* __restrict__ features,
                       const float* __restrict__ treatment,
                       const float* __restrict__ W1,
                       const float* __restrict__ b1,
                       const float* __restrict__ W2,
                       const float* __restrict__ b2,
                       const float* __restrict__ W3,
                       const float* __restrict__ b3,
                       float* __restrict__ out,
                       int level)
{
    __shared__ float sW1[kFin][kH];   // 8960 B
    __shared__ float sW2[kH][kH];     // 16384 B
    __shared__ float sb1[kH];
    __shared__ float sb2[kH];
    __shared__ float sW3[kH];
    __shared__ float sb3;

    const int tid = threadIdx.x;

    // Stage this level's weights into shared memory.
    {
        const float* w1l = W1 + (size_t)level * kFin * kH;
        float* d1 = &sW1[0][0];
        for (int i = tid; i < kFin * kH; i += kThreads) d1[i] = w1l[i];

        const float* w2l = W2 + (size_t)level * kH * kH;
        float* d2 = &sW2[0][0];
        for (int i = tid; i < kH * kH; i += kThreads) d2[i] = w2l[i];

        if (tid < kH) {
            sb1[tid] = b1[level * kH + tid];
            sb2[tid] = b2[level * kH + tid];
            sW3[tid] = W3[level * kH + tid];
        }
        if (tid == 0) sb3 = b3[level];
    }
    __syncthreads();

    const int  n    = 1 << level;
    const int  M    = kB * n;
    const bool leaf = (level == kD - 1);

    for (int row = blockIdx.x * kThreads + tid; row < M;
         row += gridDim.x * kThreads) {
        const int b = row >> level;
        const int i = row & (n - 1);
        const int g = n - 1 + i;

        // ---- gather input vector x[35] ----
        float x[kFin];
        const float4* fptr = reinterpret_cast<const float4*>(
            features + ((size_t)b * kN + g) * kF);
        #pragma unroll
        for (int q = 0; q < kF / 4; q++) {
            float4 v = fptr[q];
            x[4 * q + 0] = v.x;
            x[4 * q + 1] = v.y;
            x[4 * q + 2] = v.z;
            x[4 * q + 3] = v.w;
        }
        if (leaf) {
            x[kF + 0] = 0.0f;
            x[kF + 1] = 0.0f;
        } else {
            const float* orow = out + (size_t)b * kN;
            x[kF + 0] = orow[2 * g + 1]; // left child
            x[kF + 1] = orow[2 * g + 2]; // right child
        }
        x[kF + 2] = treatment[b];

        // ---- layer 1: h1 = relu(x @ W1 + b1) ----
        float h1[kH];
        #pragma unroll
        for (int h = 0; h < kH; h++) h1[h] = sb1[h];
        #pragma unroll
        for (int f = 0; f < kFin; f++) {
            const float xf = x[f];
            const float4* w = reinterpret_cast<const float4*>(&sW1[f][0]);
            #pragma unroll
            for (int q = 0; q < kH / 4; q++) {
                float4 wv = w[q];
                h1[4 * q + 0] = fmaf(xf, wv.x, h1[4 * q + 0]);
                h1[4 * q + 1] = fmaf(xf, wv.y, h1[4 * q + 1]);
                h1[4 * q + 2] = fmaf(xf, wv.z, h1[4 * q + 2]);
                h1[4 * q + 3] = fmaf(xf, wv.w, h1[4 * q + 3]);
            }
        }
        #pragma unroll
        for (int h = 0; h < kH; h++) h1[h] = fmaxf(h1[h], 0.0f);

        // ---- layer 2: h2 = relu(h1 @ W2 + b2) ----
        float h2[kH];
        #pragma unroll
        for (int h = 0; h < kH; h++) h2[h] = sb2[h];
        #pragma unroll
        for (int f = 0; f < kH; f++) {
            const float xf = h1[f];
            const float4* w = reinterpret_cast<const float4*>(&sW2[f][0]);
            #pragma unroll
            for (int q = 0; q < kH / 4; q++) {
                float4 wv = w[q];
                h2[4 * q + 0] = fmaf(xf, wv.x, h2[4 * q + 0]);
                h2[4 * q + 1] = fmaf(xf, wv.y, h2[4 * q + 1]);
                h2[4 * q + 2] = fmaf(xf, wv.z, h2[4 * q + 2]);
                h2[4 * q + 3] = fmaf(xf, wv.w, h2[4 * q + 3]);
            }
        }

        // ---- layer 3: y = relu(h2) @ W3 + b3 (fold relu into the dot) ----
        float y = sb3;
        #pragma unroll
        for (int h = 0; h < kH; h++) {
            y = fmaf(fmaxf(h2[h], 0.0f), sW3[h], y);
        }

        out[(size_t)b * kN + g] = y;
    }
}

} // namespace

extern "C" void kernel_launch(void* const* d_in, const int* in_sizes, int n_in,
                              void* d_out, int out_size)
{
    (void)in_sizes; (void)n_in; (void)out_size;

    const float* features  = (const float*)d_in[0];
    const float* treatment = (const float*)d_in[1];
    const float* W1        = (const float*)d_in[2];
    const float* b1        = (const float*)d_in[3];
    const float* W2        = (const float*)d_in[4];
    const float* b2        = (const float*)d_in[5];
    const float* W3        = (const float*)d_in[6];
    const float* b3        = (const float*)d_in[7];
    float*       out       = (float*)d_out;

    // Bottom-up: leaf level (10) first, root (0) last.
    for (int level = kD - 1; level >= 0; level--) {
        const int M      = kB << level;
        int blocks       = (M + kThreads - 1) / kThreads;
        if (blocks > kMaxGrid) blocks = kMaxGrid;
        tree_level_kernel<<<blocks, kThreads>>>(
            features, treatment, W1, b1, W2, b2, W3, b3, out, level);
    }
}